// round 1
// baseline (speedup 1.0000x reference)
#include <cuda_runtime.h>
#include <cuda_bf16.h>
#include <math.h>

#define NN     16384
#define EE     524288
#define F_IN   128
#define H1     256
#define H2     256
#define D1     64

// ---------------- scratch (device globals; no allocations) ----------------
__device__ float g_Xs[NN * H1];      // gemm output, pre-scaled by dinv[row] (reused both layers)
__device__ float g_h1[NN * H1];
__device__ float g_h2[NN * H2];
__device__ float g_dinv[NN];
__device__ int   g_deg[NN];
__device__ int   g_rowptr[NN + 1];
__device__ int   g_cursor[NN];
__device__ int   g_col[EE];
__device__ float g_fc1wT[H2 * D1];   // fc1_w transposed to [k][o]
__device__ float g_assign[NN * 2];
__device__ float g_gf[2 * H2];
__device__ float g_newadj[4];

// ---------------- init: deg=1 (self loop), cursor=0, accumulators=0 ----------------
__global__ void k_init() {
    int i = blockIdx.x * blockDim.x + threadIdx.x;
    if (i < NN) { g_deg[i] = 1; g_cursor[i] = 0; }
    if (i < 2 * H2) g_gf[i] = 0.0f;
    if (i < 4) g_newadj[i] = 0.0f;
}

// ---------------- in-degree histogram over dst ----------------
__global__ void k_deg(const int* __restrict__ dst) {
    int e = blockIdx.x * blockDim.x + threadIdx.x;
    if (e < EE) atomicAdd(&g_deg[dst[e]], 1);
}

__global__ void k_dinv() {
    int i = blockIdx.x * blockDim.x + threadIdx.x;
    if (i < NN) g_dinv[i] = rsqrtf((float)g_deg[i]);
}

// ---------------- exclusive scan of in-counts (deg-1) -> rowptr; 1 block ----------------
__global__ void k_scan() {
    __shared__ int part[256];
    int t = threadIdx.x;
    int base = t * 64;
    int s = 0;
    for (int j = 0; j < 64; j++) s += g_deg[base + j] - 1;
    part[t] = s;
    __syncthreads();
    for (int d = 1; d < 256; d <<= 1) {
        int v = (t >= d) ? part[t - d] : 0;
        __syncthreads();
        part[t] += v;
        __syncthreads();
    }
    int run = part[t] - s;  // exclusive prefix
    for (int j = 0; j < 64; j++) {
        g_rowptr[base + j] = run;
        run += g_deg[base + j] - 1;
    }
    if (t == 255) g_rowptr[NN] = run;
}

// ---------------- scatter edges into CSR (grouped by dst, col = src) ----------------
__global__ void k_scatter(const int* __restrict__ src, const int* __restrict__ dst) {
    int e = blockIdx.x * blockDim.x + threadIdx.x;
    if (e < EE) {
        int d = dst[e];
        int p = atomicAdd(&g_cursor[d], 1);
        g_col[g_rowptr[d] + p] = src[e];
    }
}

// ---------------- transpose fc1_w [64,256] -> [256,64] ----------------
__global__ void k_transpose(const float* __restrict__ w) {
    int i = blockIdx.x * blockDim.x + threadIdx.x;  // i = o*256 + k
    if (i < D1 * H2) {
        int o = i >> 8, k = i & 255;
        g_fc1wT[k * D1 + o] = w[i];
    }
}

// ---------------- tiled fp32 GEMM: C[r][c] = dinv[r] * sum_k A[r][k]*B[k][c] ----------------
// M=16384 (grid.y*64), Nout=256 (grid.x*64), K runtime (128 or 256)
__global__ void k_gemm(const float* __restrict__ A, const float* __restrict__ B,
                       float* __restrict__ C, int K) {
    __shared__ float As[16][65];
    __shared__ float Bs[16][65];
    int t = threadIdx.x;
    int tx = t & 15, ty = t >> 4;
    int row0 = blockIdx.y * 64, col0 = blockIdx.x * 64;
    float acc[4][4] = {};
    for (int k0 = 0; k0 < K; k0 += 16) {
        #pragma unroll
        for (int i = t; i < 64 * 16; i += 256) {
            int r = i >> 4, c = i & 15;
            As[c][r] = A[(size_t)(row0 + r) * K + k0 + c];
        }
        #pragma unroll
        for (int i = t; i < 16 * 64; i += 256) {
            int r = i >> 6, c = i & 63;
            Bs[r][c] = B[(size_t)(k0 + r) * H1 + col0 + c];
        }
        __syncthreads();
        #pragma unroll
        for (int kk = 0; kk < 16; kk++) {
            float a[4], b[4];
            #pragma unroll
            for (int i = 0; i < 4; i++) a[i] = As[kk][ty * 4 + i];
            #pragma unroll
            for (int j = 0; j < 4; j++) b[j] = Bs[kk][tx * 4 + j];
            #pragma unroll
            for (int i = 0; i < 4; i++)
                #pragma unroll
                for (int j = 0; j < 4; j++) acc[i][j] += a[i] * b[j];
        }
        __syncthreads();
    }
    #pragma unroll
    for (int i = 0; i < 4; i++) {
        int r = row0 + ty * 4 + i;
        float sc = g_dinv[r];
        #pragma unroll
        for (int j = 0; j < 4; j++)
            C[(size_t)r * H1 + col0 + tx * 4 + j] = acc[i][j] * sc;
    }
}

// ---------------- pull aggregation: out[d] = dinv[d]*(Xs[d] + sum_{s in row d} Xs[s]) + b ----------------
__global__ void k_agg(float* __restrict__ out, const float* __restrict__ bias, int relu) {
    int d = blockIdx.x;
    int t = threadIdx.x;  // 256 threads == feature dim
    float acc = g_Xs[(size_t)d * 256 + t];   // self-loop term (already dinv[d]-scaled... no: Xs scaled by dinv[src]=dinv[d])
    int s0 = g_rowptr[d], s1 = g_rowptr[d + 1];
    for (int j = s0; j < s1; j++) {
        int s = g_col[j];
        acc += g_Xs[(size_t)s * 256 + t];
    }
    float v = acc * g_dinv[d] + bias[t];
    if (relu) v = fmaxf(v, 0.0f);
    out[(size_t)d * 256 + t] = v;
}

// ---------------- per-node MLP: tanh(fc1) -> softmax(fc2) -> assign + gf partials ----------------
#define FC_NODES 64
__global__ void k_fc(const float* __restrict__ h2,
                     const float* __restrict__ fc1b,
                     const float* __restrict__ fc2w, const float* __restrict__ fc2b) {
    __shared__ float h2s[4][256];
    __shared__ float a1s[4][64];
    __shared__ float ps[4][2];
    __shared__ float gfl[2][256];
    int t = threadIdx.x;
    gfl[0][t] = 0.0f; gfl[1][t] = 0.0f;
    int n0 = blockIdx.x * FC_NODES;
    int nq = t >> 6, o = t & 63;
    for (int q = 0; q < FC_NODES; q += 4) {
        for (int i = t; i < 1024; i += 256)
            h2s[i >> 8][i & 255] = h2[(size_t)(n0 + q + (i >> 8)) * 256 + (i & 255)];
        __syncthreads();
        float dot = fc1b[o];
        #pragma unroll 8
        for (int k = 0; k < 256; k++)
            dot += g_fc1wT[k * 64 + o] * h2s[nq][k];
        a1s[nq][o] = tanhf(dot);
        __syncthreads();
        if (t < 8) {
            int n = t >> 1, c = t & 1;
            float l = fc2b[c];
            #pragma unroll
            for (int k = 0; k < 64; k++) l += fc2w[c * 64 + k] * a1s[n][k];
            ps[n][c] = l;
        }
        __syncthreads();
        if (t < 4) {
            float l0 = ps[t][0], l1 = ps[t][1];
            float m = fmaxf(l0, l1);
            float e0 = expf(l0 - m), e1 = expf(l1 - m);
            float inv = 1.0f / (e0 + e1);
            float p0 = e0 * inv, p1 = e1 * inv;
            ps[t][0] = p0; ps[t][1] = p1;
            g_assign[2 * (n0 + q + t)] = p0;
            g_assign[2 * (n0 + q + t) + 1] = p1;
        }
        __syncthreads();
        #pragma unroll
        for (int n = 0; n < 4; n++) {
            float p0 = ps[n][0], p1 = ps[n][1];
            float hv = h2s[n][t];
            gfl[0][t] += p0 * hv;
            gfl[1][t] += p1 * hv;
        }
        __syncthreads();
    }
    atomicAdd(&g_gf[t], gfl[0][t]);
    atomicAdd(&g_gf[256 + t], gfl[1][t]);
}

// ---------------- new_adj[a][b] = sum_e assign[src,a]*assign[dst,b] ----------------
__global__ void k_newadj(const int* __restrict__ src, const int* __restrict__ dst) {
    float a0 = 0, a1 = 0, a2 = 0, a3 = 0;
    for (int e = blockIdx.x * blockDim.x + threadIdx.x; e < EE; e += gridDim.x * blockDim.x) {
        int s = src[e], d = dst[e];
        float s0 = g_assign[2 * s], s1 = g_assign[2 * s + 1];
        float d0 = g_assign[2 * d], d1 = g_assign[2 * d + 1];
        a0 += s0 * d0; a1 += s0 * d1; a2 += s1 * d0; a3 += s1 * d1;
    }
    #pragma unroll
    for (int w = 16; w; w >>= 1) {
        a0 += __shfl_down_sync(0xffffffff, a0, w);
        a1 += __shfl_down_sync(0xffffffff, a1, w);
        a2 += __shfl_down_sync(0xffffffff, a2, w);
        a3 += __shfl_down_sync(0xffffffff, a3, w);
    }
    __shared__ float sa[8][4];
    int lane = threadIdx.x & 31, wid = threadIdx.x >> 5;
    if (lane == 0) { sa[wid][0] = a0; sa[wid][1] = a1; sa[wid][2] = a2; sa[wid][3] = a3; }
    __syncthreads();
    if (threadIdx.x < 4) {
        float sum = 0;
        #pragma unroll
        for (int w = 0; w < 8; w++) sum += sa[w][threadIdx.x];
        atomicAdd(&g_newadj[threadIdx.x], sum);
    }
}

// ---------------- finalize: write 769 output floats ----------------
__global__ void k_final(float* __restrict__ out) {
    int t = threadIdx.x;
    float g0 = g_gf[t], g1 = g_gf[256 + t];
    out[t]       = 0.5f * (g0 + g1);                       // graph_embedding
    out[256 + t] = fminf(fmaxf(g0, -100.0f), 100.0f);      // positive
    out[512 + t] = fminf(fmaxf(g1, -100.0f), 100.0f);      // negative
    if (t == 0) {
        float a00 = g_newadj[0], a01 = g_newadj[1], a10 = g_newadj[2], a11 = g_newadj[3];
        float den0 = fmaxf(fabsf(a00) + fabsf(a01), 1e-12f);
        float den1 = fmaxf(fabsf(a10) + fabsf(a11), 1e-12f);
        float nd0 = a00 / den0, nd1 = a11 / den1;
        out[768] = 0.5f * ((nd0 - 1.0f) * (nd0 - 1.0f) + (nd1 - 1.0f) * (nd1 - 1.0f));
    }
}

extern "C" void kernel_launch(void* const* d_in, const int* in_sizes, int n_in,
                              void* d_out, int out_size) {
    const float* features = (const float*)d_in[0];
    const int*   edges    = (const int*)d_in[1];
    const float* W1    = (const float*)d_in[2];
    const float* b1    = (const float*)d_in[3];
    const float* W2    = (const float*)d_in[4];
    const float* b2    = (const float*)d_in[5];
    const float* fc1w  = (const float*)d_in[6];
    const float* fc1b  = (const float*)d_in[7];
    const float* fc2w  = (const float*)d_in[8];
    const float* fc2b  = (const float*)d_in[9];
    float* out = (float*)d_out;
    const int* src = edges;
    const int* dst = edges + EE;

    float *pXs, *ph1, *ph2;
    cudaGetSymbolAddress((void**)&pXs, g_Xs);
    cudaGetSymbolAddress((void**)&ph1, g_h1);
    cudaGetSymbolAddress((void**)&ph2, g_h2);

    k_init<<<NN / 256, 256>>>();
    k_deg<<<EE / 256, 256>>>(dst);
    k_dinv<<<NN / 256, 256>>>();
    k_scan<<<1, 256>>>();
    k_scatter<<<EE / 256, 256>>>(src, dst);
    k_transpose<<<(D1 * H2) / 256, 256>>>(fc1w);

    dim3 gg(H1 / 64, NN / 64);
    // layer 1: Xs = (features @ W1) * dinv[row]; agg -> h1 (relu)
    k_gemm<<<gg, 256>>>(features, W1, pXs, F_IN);
    k_agg<<<NN, 256>>>(ph1, b1, 1);
    // layer 2: Xs = (h1 @ W2) * dinv[row]; agg -> h2
    k_gemm<<<gg, 256>>>(ph1, W2, pXs, H1);
    k_agg<<<NN, 256>>>(ph2, b2, 0);

    k_fc<<<NN / FC_NODES, 256>>>(ph2, fc1b, fc2w, fc2b);
    k_newadj<<<256, 256>>>(src, dst);
    k_final<<<1, 256>>>(out);
}

// round 2
// speedup vs baseline: 1.3217x; 1.3217x over previous
#include <cuda_runtime.h>
#include <cuda_bf16.h>
#include <math.h>

#define NN     16384
#define EE     524288
#define F_IN   128
#define H1     256
#define H2     256
#define D1     64

// ---------------- scratch (device globals; no allocations) ----------------
__device__ float g_Xs[NN * H1];      // gemm output, pre-scaled by dinv[row]
__device__ float g_h1[NN * H1];
__device__ float g_h2[NN * H2];
__device__ float g_dinv[NN];
__device__ int   g_deg[NN];
__device__ int   g_rowptr[NN + 1];
__device__ int   g_cursor[NN];
__device__ int   g_col[EE];
__device__ float g_fc1wT[H2 * D1];   // fc1_w transposed to [k][o]
__device__ float g_assign[NN * 2];
__device__ float g_gf[2 * H2];
__device__ float g_newadj[4];

// ---------------- init ----------------
__global__ void k_init() {
    int i = blockIdx.x * blockDim.x + threadIdx.x;
    if (i < NN) { g_deg[i] = 1; g_cursor[i] = 0; }
    if (i < 2 * H2) g_gf[i] = 0.0f;
    if (i < 4) g_newadj[i] = 0.0f;
}

// ---------------- in-degree histogram over dst ----------------
__global__ void k_deg(const int* __restrict__ dst) {
    int e = blockIdx.x * blockDim.x + threadIdx.x;
    if (e < EE) atomicAdd(&g_deg[dst[e]], 1);
}

// ---------------- fused scan + dinv: 1 block, 1024 threads, 16 elems/thread ----------------
__global__ __launch_bounds__(1024) void k_scan() {
    int t = threadIdx.x;
    int base = t * 16;
    int local[16];
    int s = 0;
    #pragma unroll
    for (int j = 0; j < 16; j++) {
        int dg = g_deg[base + j];
        g_dinv[base + j] = rsqrtf((float)dg);
        local[j] = s;
        s += dg - 1;
    }
    int lane = t & 31, wid = t >> 5;
    int v = s;
    #pragma unroll
    for (int d = 1; d < 32; d <<= 1) {
        int u = __shfl_up_sync(0xffffffffu, v, d);
        if (lane >= d) v += u;
    }
    __shared__ int wsum[32];
    if (lane == 31) wsum[wid] = v;
    __syncthreads();
    if (wid == 0) {
        int w = wsum[lane];
        #pragma unroll
        for (int d = 1; d < 32; d <<= 1) {
            int u = __shfl_up_sync(0xffffffffu, w, d);
            if (lane >= d) w += u;
        }
        wsum[lane] = w;
    }
    __syncthreads();
    int off = (v - s) + (wid ? wsum[wid - 1] : 0);
    #pragma unroll
    for (int j = 0; j < 16; j++) g_rowptr[base + j] = off + local[j];
    if (t == 1023) g_rowptr[NN] = off + s;
}

// ---------------- scatter edges into CSR ----------------
__global__ void k_scatter(const int* __restrict__ src, const int* __restrict__ dst) {
    int e = blockIdx.x * blockDim.x + threadIdx.x;
    if (e < EE) {
        int d = dst[e];
        int p = atomicAdd(&g_cursor[d], 1);
        g_col[g_rowptr[d] + p] = src[e];
    }
}

// ---------------- transpose fc1_w [64,256] -> [256,64] ----------------
__global__ void k_transpose(const float* __restrict__ w) {
    int i = blockIdx.x * blockDim.x + threadIdx.x;
    if (i < D1 * H2) {
        int o = i >> 8, k = i & 255;
        g_fc1wT[k * D1 + o] = w[i];
    }
}

// ---------------- GEMM: 128x128 tile, 8x8 per thread, C[r][c] = dinv[r]*sum_k A[r][k]*B[k][c] ----------------
#define BK 16
__global__ __launch_bounds__(256) void k_gemm(const float* __restrict__ A,
                                              const float* __restrict__ B,
                                              float* __restrict__ C, int K) {
    __shared__ float As[BK][132];
    __shared__ float Bs[BK][132];
    int t = threadIdx.x;
    int tx = t & 15, ty = t >> 4;
    int row0 = blockIdx.y * 128, col0 = blockIdx.x * 128;
    float acc[8][8] = {};

    int ar = t >> 2;                 // 0..63 (A tile row, +64 for second)
    int ac = (t & 3) << 2;           // 0,4,8,12 (k within tile)
    int br = t >> 4;                 // 0..15  (B tile row = k)
    int bc = (t & 15) << 3;          // 0..120 (col within tile)

    for (int k0 = 0; k0 < K; k0 += BK) {
        float4 va0 = *(const float4*)&A[(size_t)(row0 + ar) * K + k0 + ac];
        float4 va1 = *(const float4*)&A[(size_t)(row0 + ar + 64) * K + k0 + ac];
        As[ac + 0][ar] = va0.x; As[ac + 1][ar] = va0.y;
        As[ac + 2][ar] = va0.z; As[ac + 3][ar] = va0.w;
        As[ac + 0][ar + 64] = va1.x; As[ac + 1][ar + 64] = va1.y;
        As[ac + 2][ar + 64] = va1.z; As[ac + 3][ar + 64] = va1.w;

        const float* brow = &B[(size_t)(k0 + br) * H1 + col0 + bc];
        *(float4*)&Bs[br][bc]     = *(const float4*)(brow);
        *(float4*)&Bs[br][bc + 4] = *(const float4*)(brow + 4);
        __syncthreads();

        #pragma unroll
        for (int kk = 0; kk < BK; kk++) {
            float a[8], b[8];
            *(float4*)(a)     = *(float4*)&As[kk][ty * 8];
            *(float4*)(a + 4) = *(float4*)&As[kk][ty * 8 + 4];
            *(float4*)(b)     = *(float4*)&Bs[kk][tx * 8];
            *(float4*)(b + 4) = *(float4*)&Bs[kk][tx * 8 + 4];
            #pragma unroll
            for (int i = 0; i < 8; i++)
                #pragma unroll
                for (int j = 0; j < 8; j++) acc[i][j] += a[i] * b[j];
        }
        __syncthreads();
    }

    #pragma unroll
    for (int i = 0; i < 8; i++) {
        int r = row0 + ty * 8 + i;
        float sc = g_dinv[r];
        float4 o0 = make_float4(acc[i][0] * sc, acc[i][1] * sc, acc[i][2] * sc, acc[i][3] * sc);
        float4 o1 = make_float4(acc[i][4] * sc, acc[i][5] * sc, acc[i][6] * sc, acc[i][7] * sc);
        float* crow = &C[(size_t)r * H1 + col0 + tx * 8];
        *(float4*)(crow)     = o0;
        *(float4*)(crow + 4) = o1;
    }
}

// ---------------- pull aggregation, float4: 4 nodes/block, 64 threads/node ----------------
__global__ __launch_bounds__(256) void k_agg(float* __restrict__ out,
                                             const float* __restrict__ bias, int relu) {
    int g = threadIdx.x >> 6;
    int lane = threadIdx.x & 63;
    int d = blockIdx.x * 4 + g;
    const float4* Xs = (const float4*)g_Xs;
    float4 acc = Xs[(size_t)d * 64 + lane];   // self-loop
    int s0 = g_rowptr[d], s1 = g_rowptr[d + 1];
    for (int j = s0; j < s1; j++) {
        int s = g_col[j];
        float4 v = Xs[(size_t)s * 64 + lane];
        acc.x += v.x; acc.y += v.y; acc.z += v.z; acc.w += v.w;
    }
    float sc = g_dinv[d];
    float4 bv = ((const float4*)bias)[lane];
    float4 o;
    o.x = acc.x * sc + bv.x; o.y = acc.y * sc + bv.y;
    o.z = acc.z * sc + bv.z; o.w = acc.w * sc + bv.w;
    if (relu) {
        o.x = fmaxf(o.x, 0.0f); o.y = fmaxf(o.y, 0.0f);
        o.z = fmaxf(o.z, 0.0f); o.w = fmaxf(o.w, 0.0f);
    }
    ((float4*)out)[(size_t)d * 64 + lane] = o;
}

// ---------------- per-node MLP: tanh(fc1) -> softmax(fc2) -> assign + gf partials ----------------
#define FC_NODES 64
__global__ void k_fc(const float* __restrict__ h2,
                     const float* __restrict__ fc1b,
                     const float* __restrict__ fc2w, const float* __restrict__ fc2b) {
    __shared__ float h2s[4][256];
    __shared__ float a1s[4][64];
    __shared__ float ps[4][2];
    __shared__ float gfl[2][256];
    int t = threadIdx.x;
    gfl[0][t] = 0.0f; gfl[1][t] = 0.0f;
    int n0 = blockIdx.x * FC_NODES;
    int nq = t >> 6, o = t & 63;
    for (int q = 0; q < FC_NODES; q += 4) {
        for (int i = t; i < 1024; i += 256)
            h2s[i >> 8][i & 255] = h2[(size_t)(n0 + q + (i >> 8)) * 256 + (i & 255)];
        __syncthreads();
        float dot = fc1b[o];
        #pragma unroll 8
        for (int k = 0; k < 256; k++)
            dot += g_fc1wT[k * 64 + o] * h2s[nq][k];
        a1s[nq][o] = tanhf(dot);
        __syncthreads();
        if (t < 8) {
            int n = t >> 1, c = t & 1;
            float l = fc2b[c];
            #pragma unroll
            for (int k = 0; k < 64; k++) l += fc2w[c * 64 + k] * a1s[n][k];
            ps[n][c] = l;
        }
        __syncthreads();
        if (t < 4) {
            float l0 = ps[t][0], l1 = ps[t][1];
            float m = fmaxf(l0, l1);
            float e0 = expf(l0 - m), e1 = expf(l1 - m);
            float inv = 1.0f / (e0 + e1);
            float p0 = e0 * inv, p1 = e1 * inv;
            ps[t][0] = p0; ps[t][1] = p1;
            g_assign[2 * (n0 + q + t)] = p0;
            g_assign[2 * (n0 + q + t) + 1] = p1;
        }
        __syncthreads();
        #pragma unroll
        for (int n = 0; n < 4; n++) {
            float p0 = ps[n][0], p1 = ps[n][1];
            float hv = h2s[n][t];
            gfl[0][t] += p0 * hv;
            gfl[1][t] += p1 * hv;
        }
        __syncthreads();
    }
    atomicAdd(&g_gf[t], gfl[0][t]);
    atomicAdd(&g_gf[256 + t], gfl[1][t]);
}

// ---------------- new_adj[a][b] = sum_e assign[src,a]*assign[dst,b] ----------------
__global__ void k_newadj(const int* __restrict__ src, const int* __restrict__ dst) {
    float a0 = 0, a1 = 0, a2 = 0, a3 = 0;
    for (int e = blockIdx.x * blockDim.x + threadIdx.x; e < EE; e += gridDim.x * blockDim.x) {
        int s = src[e], d = dst[e];
        float s0 = g_assign[2 * s], s1 = g_assign[2 * s + 1];
        float d0 = g_assign[2 * d], d1 = g_assign[2 * d + 1];
        a0 += s0 * d0; a1 += s0 * d1; a2 += s1 * d0; a3 += s1 * d1;
    }
    #pragma unroll
    for (int w = 16; w; w >>= 1) {
        a0 += __shfl_down_sync(0xffffffff, a0, w);
        a1 += __shfl_down_sync(0xffffffff, a1, w);
        a2 += __shfl_down_sync(0xffffffff, a2, w);
        a3 += __shfl_down_sync(0xffffffff, a3, w);
    }
    __shared__ float sa[8][4];
    int lane = threadIdx.x & 31, wid = threadIdx.x >> 5;
    if (lane == 0) { sa[wid][0] = a0; sa[wid][1] = a1; sa[wid][2] = a2; sa[wid][3] = a3; }
    __syncthreads();
    if (threadIdx.x < 4) {
        float sum = 0;
        #pragma unroll
        for (int w = 0; w < 8; w++) sum += sa[w][threadIdx.x];
        atomicAdd(&g_newadj[threadIdx.x], sum);
    }
}

// ---------------- finalize ----------------
__global__ void k_final(float* __restrict__ out) {
    int t = threadIdx.x;
    float g0 = g_gf[t], g1 = g_gf[256 + t];
    out[t]       = 0.5f * (g0 + g1);
    out[256 + t] = fminf(fmaxf(g0, -100.0f), 100.0f);
    out[512 + t] = fminf(fmaxf(g1, -100.0f), 100.0f);
    if (t == 0) {
        float a00 = g_newadj[0], a01 = g_newadj[1], a10 = g_newadj[2], a11 = g_newadj[3];
        float den0 = fmaxf(fabsf(a00) + fabsf(a01), 1e-12f);
        float den1 = fmaxf(fabsf(a10) + fabsf(a11), 1e-12f);
        float nd0 = a00 / den0, nd1 = a11 / den1;
        out[768] = 0.5f * ((nd0 - 1.0f) * (nd0 - 1.0f) + (nd1 - 1.0f) * (nd1 - 1.0f));
    }
}

extern "C" void kernel_launch(void* const* d_in, const int* in_sizes, int n_in,
                              void* d_out, int out_size) {
    const float* features = (const float*)d_in[0];
    const int*   edges    = (const int*)d_in[1];
    const float* W1    = (const float*)d_in[2];
    const float* b1    = (const float*)d_in[3];
    const float* W2    = (const float*)d_in[4];
    const float* b2    = (const float*)d_in[5];
    const float* fc1w  = (const float*)d_in[6];
    const float* fc1b  = (const float*)d_in[7];
    const float* fc2w  = (const float*)d_in[8];
    const float* fc2b  = (const float*)d_in[9];
    float* out = (float*)d_out;
    const int* src = edges;
    const int* dst = edges + EE;

    float *pXs, *ph1, *ph2;
    cudaGetSymbolAddress((void**)&pXs, g_Xs);
    cudaGetSymbolAddress((void**)&ph1, g_h1);
    cudaGetSymbolAddress((void**)&ph2, g_h2);

    k_init<<<NN / 256, 256>>>();
    k_deg<<<EE / 256, 256>>>(dst);
    k_scan<<<1, 1024>>>();
    k_scatter<<<EE / 256, 256>>>(src, dst);
    k_transpose<<<(D1 * H2) / 256, 256>>>(fc1w);

    dim3 gg(H1 / 128, NN / 128);
    k_gemm<<<gg, 256>>>(features, W1, pXs, F_IN);
    k_agg<<<NN / 4, 256>>>(ph1, b1, 1);
    k_gemm<<<gg, 256>>>(ph1, W2, pXs, H1);
    k_agg<<<NN / 4, 256>>>(ph2, b2, 0);

    k_fc<<<NN / FC_NODES, 256>>>(ph2, fc1b, fc2w, fc2b);
    k_newadj<<<256, 256>>>(src, dst);
    k_final<<<1, 256>>>(out);
}

// round 4
// speedup vs baseline: 1.4871x; 1.1252x over previous
#include <cuda_runtime.h>
#include <cuda_bf16.h>
#include <cstdint>
#include <math.h>

#define NN     16384
#define EE     524288
#define F_IN   128
#define H1     256
#define H2     256
#define D1     64

// ---------------- scratch (device globals; no allocations) ----------------
__device__ float g_Y[NN * F_IN];     // dinv[r]*features
__device__ float g_Z[NN * F_IN];     // aggregated features (layer-1 pre-GEMM)
__device__ float g_Xs[NN * H1];      // layer-2 gemm output, dinv-scaled
__device__ float g_h1[NN * H1];
__device__ float g_h2[NN * H2];
__device__ float g_dinv[NN];
__device__ int   g_deg[NN];
__device__ int   g_rowptr[NN + 1];
__device__ int   g_cursor[NN];
__device__ int   g_col[EE];
__device__ float g_fc1wT[H2 * D1];
__device__ float g_assign[NN * 2];
__device__ float g_gf[2 * H2];
__device__ float g_newadj[4];

// ---------------- init ----------------
__global__ void k_init() {
    int i = blockIdx.x * blockDim.x + threadIdx.x;
    if (i < NN) { g_deg[i] = 1; g_cursor[i] = 0; }
    if (i < 2 * H2) g_gf[i] = 0.0f;
    if (i < 4) g_newadj[i] = 0.0f;
}

__global__ void k_deg(const int* __restrict__ dst) {
    int e = blockIdx.x * blockDim.x + threadIdx.x;
    if (e < EE) atomicAdd(&g_deg[dst[e]], 1);
}

// ---------------- fused scan + dinv: 1 block, 1024 threads ----------------
__global__ __launch_bounds__(1024) void k_scan() {
    int t = threadIdx.x;
    int base = t * 16;
    int local[16];
    int s = 0;
    #pragma unroll
    for (int j = 0; j < 16; j++) {
        int dg = g_deg[base + j];
        g_dinv[base + j] = rsqrtf((float)dg);
        local[j] = s;
        s += dg - 1;
    }
    int lane = t & 31, wid = t >> 5;
    int v = s;
    #pragma unroll
    for (int d = 1; d < 32; d <<= 1) {
        int u = __shfl_up_sync(0xffffffffu, v, d);
        if (lane >= d) v += u;
    }
    __shared__ int wsum[32];
    if (lane == 31) wsum[wid] = v;
    __syncthreads();
    if (wid == 0) {
        int w = wsum[lane];
        #pragma unroll
        for (int d = 1; d < 32; d <<= 1) {
            int u = __shfl_up_sync(0xffffffffu, w, d);
            if (lane >= d) w += u;
        }
        wsum[lane] = w;
    }
    __syncthreads();
    int off = (v - s) + (wid ? wsum[wid - 1] : 0);
    #pragma unroll
    for (int j = 0; j < 16; j++) g_rowptr[base + j] = off + local[j];
    if (t == 1023) g_rowptr[NN] = off + s;
}

__global__ void k_scatter(const int* __restrict__ src, const int* __restrict__ dst) {
    int e = blockIdx.x * blockDim.x + threadIdx.x;
    if (e < EE) {
        int d = dst[e];
        int p = atomicAdd(&g_cursor[d], 1);
        g_col[g_rowptr[d] + p] = src[e];
    }
}

__global__ void k_transpose(const float* __restrict__ w) {
    int i = blockIdx.x * blockDim.x + threadIdx.x;
    if (i < D1 * H2) {
        int o = i >> 8, k = i & 255;
        g_fc1wT[k * D1 + o] = w[i];
    }
}

// ---------------- Y = dinv[r] * features ----------------
__global__ void k_pre1(const float* __restrict__ X) {
    int i = blockIdx.x * blockDim.x + threadIdx.x;   // float4 index
    int node = i >> 5;                               // 32 float4 per node
    float sc = g_dinv[node];
    float4 v = ((const float4*)X)[i];
    v.x *= sc; v.y *= sc; v.z *= sc; v.w *= sc;
    ((float4*)g_Y)[i] = v;
}

// ---------------- layer-1 aggregation (128-wide): Z[d] = dinv[d]*(Y[d]+sum Y[s]) ----------------
__global__ __launch_bounds__(256) void k_agg1() {
    int gi = threadIdx.x >> 5;
    int lane = threadIdx.x & 31;
    int d = blockIdx.x * 8 + gi;
    const float4* Y = (const float4*)g_Y;
    float4 acc = Y[(size_t)d * 32 + lane];
    int s0 = g_rowptr[d], s1 = g_rowptr[d + 1];
    for (int j = s0; j < s1; j++) {
        int s = g_col[j];
        float4 v = Y[(size_t)s * 32 + lane];
        acc.x += v.x; acc.y += v.y; acc.z += v.z; acc.w += v.w;
    }
    float sc = g_dinv[d];
    acc.x *= sc; acc.y *= sc; acc.z *= sc; acc.w *= sc;
    ((float4*)g_Z)[(size_t)d * 32 + lane] = acc;
}

// ---------------- tf32 tensor-core GEMM ----------------
// C[16384 x 256] = A[16384 x K] @ B[K x 256]
// mode 0: C = relu(AB + bias)   mode 1: C = dinv[row] * AB
__device__ __forceinline__ unsigned int f2tf32(float x) {
    unsigned int r;
    asm("cvt.rna.tf32.f32 %0, %1;" : "=r"(r) : "f"(x));
    return r;
}
__device__ __forceinline__ void mma_tf32(float* d, const unsigned int* a, const unsigned int* b) {
    asm volatile(
        "mma.sync.aligned.m16n8k8.row.col.f32.tf32.tf32.f32 "
        "{%0,%1,%2,%3},{%4,%5,%6,%7},{%8,%9},{%0,%1,%2,%3};\n"
        : "+f"(d[0]), "+f"(d[1]), "+f"(d[2]), "+f"(d[3])
        : "r"(a[0]), "r"(a[1]), "r"(a[2]), "r"(a[3]), "r"(b[0]), "r"(b[1]));
}

#define GBK 32
__global__ __launch_bounds__(256) void k_gemm_tc(const float* __restrict__ A,
                                                 const float* __restrict__ B,
                                                 float* __restrict__ C,
                                                 const float* __restrict__ bias,
                                                 int K, int mode) {
    __shared__ unsigned int As[GBK][136];   // [k][row], tf32 bits
    __shared__ unsigned int Bs[GBK][136];   // [k][col], tf32 bits
    int t = threadIdx.x;
    int row0 = blockIdx.y * 128, col0 = blockIdx.x * 128;
    int wid = t >> 5, lane = t & 31;
    int wr = wid >> 2, wc = wid & 3;       // warp tile: rows wr*64, cols wc*32
    int g = lane >> 2, tig = lane & 3;
    float acc[4][4][4] = {};

    for (int k0 = 0; k0 < K; k0 += GBK) {
        #pragma unroll
        for (int j = 0; j < 4; j++) {
            int i = t + 256 * j;
            int r = i >> 3, kq = (i & 7) * 4;      // 8 float4 per 32-wide k row
            float4 v = *(const float4*)&A[(size_t)(row0 + r) * K + k0 + kq];
            As[kq + 0][r] = f2tf32(v.x); As[kq + 1][r] = f2tf32(v.y);
            As[kq + 2][r] = f2tf32(v.z); As[kq + 3][r] = f2tf32(v.w);
        }
        #pragma unroll
        for (int j = 0; j < 4; j++) {
            int i = t + 256 * j;
            int kr = i >> 5, nq = (i & 31) * 4;    // 32 float4 per 128-wide n row
            float4 v = *(const float4*)&B[(size_t)(k0 + kr) * 256 + col0 + nq];
            Bs[kr][nq + 0] = f2tf32(v.x); Bs[kr][nq + 1] = f2tf32(v.y);
            Bs[kr][nq + 2] = f2tf32(v.z); Bs[kr][nq + 3] = f2tf32(v.w);
        }
        __syncthreads();

        #pragma unroll
        for (int kk = 0; kk < GBK; kk += 8) {
            unsigned int af[4][4], bf[4][2];
            #pragma unroll
            for (int mi = 0; mi < 4; mi++) {
                int r = wr * 64 + mi * 16 + g;
                af[mi][0] = As[kk + tig][r];
                af[mi][1] = As[kk + tig][r + 8];
                af[mi][2] = As[kk + tig + 4][r];
                af[mi][3] = As[kk + tig + 4][r + 8];
            }
            #pragma unroll
            for (int ni = 0; ni < 4; ni++) {
                int c = wc * 32 + ni * 8 + g;
                bf[ni][0] = Bs[kk + tig][c];
                bf[ni][1] = Bs[kk + tig + 4][c];
            }
            #pragma unroll
            for (int mi = 0; mi < 4; mi++)
                #pragma unroll
                for (int ni = 0; ni < 4; ni++)
                    mma_tf32(acc[mi][ni], af[mi], bf[ni]);
        }
        __syncthreads();
    }

    #pragma unroll
    for (int mi = 0; mi < 4; mi++) {
        #pragma unroll
        for (int half = 0; half < 2; half++) {
            int r = row0 + wr * 64 + mi * 16 + g + half * 8;
            float sc = (mode == 1) ? g_dinv[r] : 1.0f;
            #pragma unroll
            for (int ni = 0; ni < 4; ni++) {
                int c = col0 + wc * 32 + ni * 8 + tig * 2;
                float v0 = acc[mi][ni][half * 2 + 0];
                float v1 = acc[mi][ni][half * 2 + 1];
                if (mode == 0) {
                    v0 = fmaxf(v0 + bias[c], 0.0f);
                    v1 = fmaxf(v1 + bias[c + 1], 0.0f);
                } else {
                    v0 *= sc; v1 *= sc;
                }
                *(float2*)&C[(size_t)r * 256 + c] = make_float2(v0, v1);
            }
        }
    }
}

// ---------------- layer-2 aggregation (256-wide) ----------------
__global__ __launch_bounds__(256) void k_agg(float* __restrict__ out,
                                             const float* __restrict__ bias, int relu) {
    int gi = threadIdx.x >> 6;
    int lane = threadIdx.x & 63;
    int d = blockIdx.x * 4 + gi;
    const float4* Xs = (const float4*)g_Xs;
    float4 acc = Xs[(size_t)d * 64 + lane];
    int s0 = g_rowptr[d], s1 = g_rowptr[d + 1];
    for (int j = s0; j < s1; j++) {
        int s = g_col[j];
        float4 v = Xs[(size_t)s * 64 + lane];
        acc.x += v.x; acc.y += v.y; acc.z += v.z; acc.w += v.w;
    }
    float sc = g_dinv[d];
    float4 bv = ((const float4*)bias)[lane];
    float4 o;
    o.x = acc.x * sc + bv.x; o.y = acc.y * sc + bv.y;
    o.z = acc.z * sc + bv.z; o.w = acc.w * sc + bv.w;
    if (relu) {
        o.x = fmaxf(o.x, 0.0f); o.y = fmaxf(o.y, 0.0f);
        o.z = fmaxf(o.z, 0.0f); o.w = fmaxf(o.w, 0.0f);
    }
    ((float4*)out)[(size_t)d * 64 + lane] = o;
}

// ---------------- per-node MLP ----------------
#define FC_NODES 64
__global__ void k_fc(const float* __restrict__ h2,
                     const float* __restrict__ fc1b,
                     const float* __restrict__ fc2w, const float* __restrict__ fc2b) {
    __shared__ float h2s[4][256];
    __shared__ float a1s[4][64];
    __shared__ float ps[4][2];
    __shared__ float gfl[2][256];
    int t = threadIdx.x;
    gfl[0][t] = 0.0f; gfl[1][t] = 0.0f;
    int n0 = blockIdx.x * FC_NODES;
    int nq = t >> 6, o = t & 63;
    for (int q = 0; q < FC_NODES; q += 4) {
        for (int i = t; i < 1024; i += 256)
            h2s[i >> 8][i & 255] = h2[(size_t)(n0 + q + (i >> 8)) * 256 + (i & 255)];
        __syncthreads();
        float dot = fc1b[o];
        #pragma unroll 8
        for (int k = 0; k < 256; k++)
            dot += g_fc1wT[k * 64 + o] * h2s[nq][k];
        a1s[nq][o] = tanhf(dot);
        __syncthreads();
        if (t < 8) {
            int n = t >> 1, c = t & 1;
            float l = fc2b[c];
            #pragma unroll
            for (int k = 0; k < 64; k++) l += fc2w[c * 64 + k] * a1s[n][k];
            ps[n][c] = l;
        }
        __syncthreads();
        if (t < 4) {
            float l0 = ps[t][0], l1 = ps[t][1];
            float m = fmaxf(l0, l1);
            float e0 = expf(l0 - m), e1 = expf(l1 - m);
            float inv = 1.0f / (e0 + e1);
            float p0 = e0 * inv, p1 = e1 * inv;
            ps[t][0] = p0; ps[t][1] = p1;
            g_assign[2 * (n0 + q + t)] = p0;
            g_assign[2 * (n0 + q + t) + 1] = p1;
        }
        __syncthreads();
        #pragma unroll
        for (int n = 0; n < 4; n++) {
            float p0 = ps[n][0], p1 = ps[n][1];
            float hv = h2s[n][t];
            gfl[0][t] += p0 * hv;
            gfl[1][t] += p1 * hv;
        }
        __syncthreads();
    }
    atomicAdd(&g_gf[t], gfl[0][t]);
    atomicAdd(&g_gf[256 + t], gfl[1][t]);
}

// ---------------- new_adj ----------------
__global__ void k_newadj(const int* __restrict__ src, const int* __restrict__ dst) {
    float a0 = 0, a1 = 0, a2 = 0, a3 = 0;
    for (int e = blockIdx.x * blockDim.x + threadIdx.x; e < EE; e += gridDim.x * blockDim.x) {
        int s = src[e], d = dst[e];
        float s0 = g_assign[2 * s], s1 = g_assign[2 * s + 1];
        float d0 = g_assign[2 * d], d1 = g_assign[2 * d + 1];
        a0 += s0 * d0; a1 += s0 * d1; a2 += s1 * d0; a3 += s1 * d1;
    }
    #pragma unroll
    for (int w = 16; w; w >>= 1) {
        a0 += __shfl_down_sync(0xffffffff, a0, w);
        a1 += __shfl_down_sync(0xffffffff, a1, w);
        a2 += __shfl_down_sync(0xffffffff, a2, w);
        a3 += __shfl_down_sync(0xffffffff, a3, w);
    }
    __shared__ float sa[8][4];
    int lane = threadIdx.x & 31, wid = threadIdx.x >> 5;
    if (lane == 0) { sa[wid][0] = a0; sa[wid][1] = a1; sa[wid][2] = a2; sa[wid][3] = a3; }
    __syncthreads();
    if (threadIdx.x < 4) {
        float sum = 0;
        #pragma unroll
        for (int w = 0; w < 8; w++) sum += sa[w][threadIdx.x];
        atomicAdd(&g_newadj[threadIdx.x], sum);
    }
}

// ---------------- finalize ----------------
__global__ void k_final(float* __restrict__ out) {
    int t = threadIdx.x;
    float g0 = g_gf[t], g1 = g_gf[256 + t];
    out[t]       = 0.5f * (g0 + g1);
    out[256 + t] = fminf(fmaxf(g0, -100.0f), 100.0f);
    out[512 + t] = fminf(fmaxf(g1, -100.0f), 100.0f);
    if (t == 0) {
        float a00 = g_newadj[0], a01 = g_newadj[1], a10 = g_newadj[2], a11 = g_newadj[3];
        float den0 = fmaxf(fabsf(a00) + fabsf(a01), 1e-12f);
        float den1 = fmaxf(fabsf(a10) + fabsf(a11), 1e-12f);
        float nd0 = a00 / den0, nd1 = a11 / den1;
        out[768] = 0.5f * ((nd0 - 1.0f) * (nd0 - 1.0f) + (nd1 - 1.0f) * (nd1 - 1.0f));
    }
}

extern "C" void kernel_launch(void* const* d_in, const int* in_sizes, int n_in,
                              void* d_out, int out_size) {
    const float* features = (const float*)d_in[0];
    const int*   edges    = (const int*)d_in[1];
    const float* W1    = (const float*)d_in[2];
    const float* b1    = (const float*)d_in[3];
    const float* W2    = (const float*)d_in[4];
    const float* b2    = (const float*)d_in[5];
    const float* fc1w  = (const float*)d_in[6];
    const float* fc1b  = (const float*)d_in[7];
    const float* fc2w  = (const float*)d_in[8];
    const float* fc2b  = (const float*)d_in[9];
    float* out = (float*)d_out;
    const int* src = edges;
    const int* dst = edges + EE;

    float *pXs, *ph1, *ph2, *pZ;
    cudaGetSymbolAddress((void**)&pXs, g_Xs);
    cudaGetSymbolAddress((void**)&ph1, g_h1);
    cudaGetSymbolAddress((void**)&ph2, g_h2);
    cudaGetSymbolAddress((void**)&pZ,  g_Z);

    k_init<<<NN / 256, 256>>>();
    k_deg<<<EE / 256, 256>>>(dst);
    k_scan<<<1, 1024>>>();
    k_scatter<<<EE / 256, 256>>>(src, dst);
    k_transpose<<<(D1 * H2) / 256, 256>>>(fc1w);

    // layer 1: aggregate-then-transform (aggregation on 128-wide raw features)
    k_pre1<<<(NN * F_IN / 4) / 256, 256>>>(features);
    k_agg1<<<NN / 8, 256>>>();
    dim3 gg(2, NN / 128);
    k_gemm_tc<<<gg, 256>>>(pZ, W1, ph1, b1, F_IN, 0);     // h1 = relu(Z@W1+b1)

    // layer 2: transform-then-aggregate
    k_gemm_tc<<<gg, 256>>>(ph1, W2, pXs, (const float*)0, H1, 1);  // Xs = dinv*(h1@W2)
    k_agg<<<NN / 4, 256>>>(ph2, b2, 0);

    k_fc<<<NN / FC_NODES, 256>>>(ph2, fc1b, fc2w, fc2b);
    k_newadj<<<256, 256>>>(src, dst);
    k_final<<<1, 256>>>(out);
}